// round 15
// baseline (speedup 1.0000x reference)
#include <cuda_runtime.h>
#include <cstdint>

#define D 256
#define BT 2048   // B*T
#define NST 3     // cp.async pipeline stages
#define KTILES 8  // K=256 in 32-float tiles
#define NCTA 384
#define NTHR 256

// Scratch (static device globals — no allocation).
__device__ float g_Q[BT * D];
__device__ float g_K[BT * D];
__device__ float g_V[BT * D];

// Grid barrier state: monotonic generation, count auto-resets each use.
__device__ unsigned g_count = 0;
__device__ unsigned g_gen   = 0;

// ---------------------------------------------------------------------------
// helpers
// ---------------------------------------------------------------------------
__device__ __forceinline__ uint32_t smem_u32(const void* p) {
    uint32_t a;
    asm("{ .reg .u64 t; cvta.to.shared.u64 t, %1; cvt.u32.u64 %0, t; }"
        : "=r"(a) : "l"(p));
    return a;
}
__device__ __forceinline__ void ldm_x4(uint32_t& r0, uint32_t& r1,
                                       uint32_t& r2, uint32_t& r3, uint32_t a) {
    asm volatile("ldmatrix.sync.aligned.m8n8.x4.shared.b16 {%0,%1,%2,%3}, [%4];"
                 : "=r"(r0), "=r"(r1), "=r"(r2), "=r"(r3) : "r"(a));
}
// m16n8k8 TF32 MMA. A frag 4 regs, B frag 2 regs, C/D 4 f32.
__device__ __forceinline__ void mma168_tf32(float* c, const uint32_t* a,
                                            const uint32_t* b) {
    asm volatile(
        "mma.sync.aligned.m16n8k8.row.col.f32.tf32.tf32.f32 "
        "{%0,%1,%2,%3}, {%4,%5,%6,%7}, {%8,%9}, {%0,%1,%2,%3};"
        : "+f"(c[0]), "+f"(c[1]), "+f"(c[2]), "+f"(c[3])
        : "r"(a[0]), "r"(a[1]), "r"(a[2]), "r"(a[3]), "r"(b[0]), "r"(b[1]));
}
__device__ __forceinline__ void cpa16(uint32_t s, const void* g) {
    asm volatile("cp.async.cg.shared.global [%0], [%1], 16;"
                 :: "r"(s), "l"(g) : "memory");
}
#define CP_COMMIT() asm volatile("cp.async.commit_group;" ::: "memory")
#define CP_WAIT1()  asm volatile("cp.async.wait_group 1;" ::: "memory")

// Round f32 bits to nearest tf32 (13 low mantissa bits): +0x1000, HW truncates.
#define RN_TF32(r) ((r) + 0x1000u)

// 128B rows, 8 x 16B chunks, full XOR swizzle: chunk ^= row&7.
#define SWOFF2(row, c) ((row) * 128 + ((((c) ^ ((row) & 7))) << 4))

// Software grid barrier. Requires all NCTA CTAs co-resident
// (enforced by __launch_bounds__(256,3): 3 CTAs/SM x 148 = 444 >= 384).
__device__ __forceinline__ void grid_barrier() {
    __syncthreads();
    if (threadIdx.x == 0) {
        __threadfence();
        volatile unsigned* genp = &g_gen;
        const unsigned gen = *genp;
        const unsigned a = atomicAdd(&g_count, 1u);
        if (a == NCTA - 1) {
            atomicExch(&g_count, 0u);
            __threadfence();
            *genp = gen + 1;
        } else {
            while (*genp == gen) { }
            __threadfence();
        }
    }
    __syncthreads();
}

// ---------------------------------------------------------------------------
// Fused: TF32 GEMM (384 tile-jobs) -> grid barrier -> Taylor attention.
// ---------------------------------------------------------------------------
__global__ void __launch_bounds__(NTHR, 3) fused_kernel(
    const float* __restrict__ X,
    const float* __restrict__ Wq, const float* __restrict__ Wk,
    const float* __restrict__ Wv,
    const float* __restrict__ bq, const float* __restrict__ bk,
    const float* __restrict__ bv, float* __restrict__ out)
{
    __shared__ __align__(16) char sA[NST][64 * 128];   // 24KB
    __shared__ __align__(16) char sB[NST][64 * 128];   // 24KB

    const int tid  = threadIdx.x;
    const int lane = tid & 31;
    const int wid  = tid >> 5;
    const int cta  = blockIdx.x;

    // ================= Phase 1: GEMM tile-job =================
    // cta -> (z, col0, row0): z = cta/128; col0 = ((cta%128)>>5)*64;
    // row0 = (cta&31)*64. Warp tile 16(M) x 32(N), warp grid 4x2.
    {
        const int z    = cta >> 7;
        const int rem  = cta & 127;
        const int col0 = (rem >> 5) * 64;
        const int row0 = (rem & 31) * 64;
        const int warp_m = wid & 3;
        const int warp_n = wid >> 2;

        const float* Wg   = (z == 0) ? Wq : (z == 1) ? Wk : Wv;
        const float* bias = (z == 0) ? bq : (z == 1) ? bk : bv;
        float* Cw = (z == 0) ? g_Q : (z == 1) ? g_K : g_V;

        // loader: thread -> (row, 2 x 16B chunks)
        const int lrow  = tid >> 2;
        const int cbase = (tid & 3) * 2;
        const float* agp = X  + (size_t)(row0 + lrow) * D + cbase * 4;
        const float* bgp = Wg + (size_t)(col0 + lrow) * D + cbase * 4;
        const uint32_t sA_base = smem_u32(sA);
        const uint32_t sB_base = smem_u32(sB);
        uint32_t saoff[2], sboff[2];
        #pragma unroll
        for (int j = 0; j < 2; j++) {
            saoff[j] = sA_base + SWOFF2(lrow, cbase + j);
            sboff[j] = sB_base + SWOFF2(lrow, cbase + j);
        }

        // ldmatrix fragment addresses over 4 k8-steps per 128B row
        uint32_t aaddr[4], baddr[2][4];
        {
            const int m = lane >> 3;
            const int ar  = ((m & 1) << 3) + (lane & 7);
            const int akc = m >> 1;
            const int bn  = ((m >> 1) << 3) + (lane & 7);
            const int bkc = m & 1;
            {
                const int row = warp_m * 16 + ar;
                #pragma unroll
                for (int h = 0; h < 4; h++)
                    aaddr[h] = sA_base + SWOFF2(row, akc + 2 * h);
            }
            #pragma unroll
            for (int g = 0; g < 2; g++) {
                const int row = warp_n * 32 + g * 16 + bn;
                #pragma unroll
                for (int h = 0; h < 4; h++)
                    baddr[g][h] = sB_base + SWOFF2(row, bkc + 2 * h);
            }
        }

        float acc[4][4];
        #pragma unroll
        for (int g = 0; g < 4; g++)
            #pragma unroll
            for (int i = 0; i < 4; i++) acc[g][i] = 0.f;

        // prologue: stages 0,1
        #pragma unroll
        for (int st = 0; st < NST - 1; st++) {
            const uint32_t so = st * 8192;
            #pragma unroll
            for (int j = 0; j < 2; j++) {
                cpa16(saoff[j] + so, agp + st * 32 + j * 4);
                cpa16(sboff[j] + so, bgp + st * 32 + j * 4);
            }
            CP_COMMIT();
        }

        int sbuf = 0;
        for (int it = 0; it < KTILES; it++) {
            CP_WAIT1();
            __syncthreads();

            const int nst = it + NST - 1;
            if (nst < KTILES) {
                const int nb = (sbuf + 2 >= NST) ? sbuf + 2 - NST : sbuf + 2;
                const uint32_t so = nb * 8192;
                #pragma unroll
                for (int j = 0; j < 2; j++) {
                    cpa16(saoff[j] + so, agp + nst * 32 + j * 4);
                    cpa16(sboff[j] + so, bgp + nst * 32 + j * 4);
                }
            }
            CP_COMMIT();

            const uint32_t so = sbuf * 8192;
            #pragma unroll
            for (int h = 0; h < 4; h++) {
                uint32_t af[4], bfr[2][4];
                ldm_x4(af[0], af[1], af[2], af[3], aaddr[h] + so);
                ldm_x4(bfr[0][0], bfr[0][1], bfr[0][2], bfr[0][3],
                       baddr[0][h] + so);
                ldm_x4(bfr[1][0], bfr[1][1], bfr[1][2], bfr[1][3],
                       baddr[1][h] + so);
                #pragma unroll
                for (int i = 0; i < 4; i++) af[i] = RN_TF32(af[i]);
                #pragma unroll
                for (int g = 0; g < 2; g++)
                    #pragma unroll
                    for (int i = 0; i < 4; i++) bfr[g][i] = RN_TF32(bfr[g][i]);
                #pragma unroll
                for (int g = 0; g < 2; g++) {
                    mma168_tf32(acc[2 * g + 0], af, &bfr[g][0]);
                    mma168_tf32(acc[2 * g + 1], af, &bfr[g][2]);
                }
            }
            sbuf = (sbuf + 1 >= NST) ? 0 : sbuf + 1;
        }

        // epilogue: add bias, store fp32
        const int tg = lane >> 2;
        const int tc = (lane & 3) * 2;
        const int rbase = row0 + warp_m * 16 + tg;
        #pragma unroll
        for (int g = 0; g < 4; g++) {
            const int c = col0 + warp_n * 32 + g * 8 + tc;
            const float b0 = bias[c], b1 = bias[c + 1];
            float2 v0 = { acc[g][0] + b0, acc[g][1] + b1 };
            float2 v1 = { acc[g][2] + b0, acc[g][3] + b1 };
            *(float2*)&Cw[(size_t)rbase * D + c]       = v0;
            *(float2*)&Cw[(size_t)(rbase + 8) * D + c] = v1;
        }
    }

    grid_barrier();

    // ================= Phase 2: attention (1 token per warp) =================
    // 3072 warps, tokens assigned to warp_gid < 2048.
    {
        const int warp_gid = cta * 8 + wid;
        if (warp_gid < BT) {
            const int base = warp_gid * D;
            const int eb = base + lane * 8;
            const float s = 1.0f / 16.0f;

            float4 k4a = *(const float4*)&g_K[eb];
            float4 k4b = *(const float4*)&g_K[eb + 4];
            float4 v4a = *(const float4*)&g_V[eb];
            float4 v4b = *(const float4*)&g_V[eb + 4];
            float4 q4a = *(const float4*)&g_Q[eb];
            float4 q4b = *(const float4*)&g_Q[eb + 4];

            float kv[8] = { k4a.x * s, k4a.y * s, k4a.z * s, k4a.w * s,
                            k4b.x * s, k4b.y * s, k4b.z * s, k4b.w * s };
            float vv[8] = { v4a.x, v4a.y, v4a.z, v4a.w,
                            v4b.x, v4b.y, v4b.z, v4b.w };
            float qv[8] = { q4a.x, q4a.y, q4a.z, q4a.w,
                            q4b.x, q4b.y, q4b.z, q4b.w };

            float m[13], M[13];
            #pragma unroll
            for (int n = 0; n < 13; n++) { m[n] = 0.f; M[n] = 0.f; }
            #pragma unroll
            for (int u = 0; u < 8; u++) {
                const float k1 = kv[u], v1 = vv[u];
                M[0] += v1;
                float kp = k1;
                m[1] += kp; M[1] += kp * v1;
                #pragma unroll
                for (int n = 2; n <= 12; n++) {
                    kp *= k1;
                    m[n] += kp;
                    M[n] += kp * v1;
                }
            }
            m[0] = 8.0f;

            #pragma unroll
            for (int off = 16; off; off >>= 1) {
                #pragma unroll
                for (int n = 0; n < 13; n++) {
                    m[n] += __shfl_xor_sync(0xFFFFFFFFu, m[n], off);
                    M[n] += __shfl_xor_sync(0xFFFFFFFFu, M[n], off);
                }
            }

            const float invf[13] = {
                1.f, 1.f, 0.5f, 1.f/6.f, 1.f/24.f, 1.f/120.f, 1.f/720.f,
                1.f/5040.f, 1.f/40320.f, 1.f/362880.f, 1.f/3628800.f,
                1.f/39916800.f, 1.f/479001600.f };
            #pragma unroll
            for (int n = 2; n < 13; n++) { m[n] *= invf[n]; M[n] *= invf[n]; }

            float res[8];
            #pragma unroll
            for (int u = 0; u < 8; u++) {
                const float q = qv[u];
                float num = M[12], den = m[12];
                #pragma unroll
                for (int n = 11; n >= 0; n--) {
                    num = num * q + M[n];
                    den = den * q + m[n];
                }
                res[u] = __fdividef(num, den);
            }
            *(float4*)&out[eb] =
                make_float4(res[0], res[1], res[2], res[3]);
            *(float4*)&out[eb + 4] =
                make_float4(res[4], res[5], res[6], res[7]);
        }
    }
}

// ---------------------------------------------------------------------------
// Launch. Inputs: x, Wq, bq, Wk, bk, Wv, bv. Output fp32 [2,1024,256].
// ---------------------------------------------------------------------------
extern "C" void kernel_launch(void* const* d_in, const int* in_sizes, int n_in,
                              void* d_out, int out_size)
{
    const float* x  = (const float*)d_in[0];
    const float* Wq = (const float*)d_in[1];
    const float* bq = (const float*)d_in[2];
    const float* Wk = (const float*)d_in[3];
    const float* bk = (const float*)d_in[4];
    const float* Wv = (const float*)d_in[5];
    const float* bv = (const float*)d_in[6];
    float* out = (float*)d_out;

    fused_kernel<<<NCTA, NTHR>>>(x, Wq, Wk, Wv, bq, bk, bv, out);
}

// round 16
// speedup vs baseline: 1.0345x; 1.0345x over previous
#include <cuda_runtime.h>
#include <cstdint>

#define D 256
#define BT 2048   // B*T
#define NST 4     // cp.async pipeline stages (2 tile-loads in flight)
#define KTILES 8  // K=256 in 32-float tiles

// Scratch (static device globals — no allocation).
__device__ float g_Q[BT * D];
__device__ float g_K[BT * D];
__device__ float g_V[BT * D];

// ---------------------------------------------------------------------------
// helpers
// ---------------------------------------------------------------------------
__device__ __forceinline__ uint32_t smem_u32(const void* p) {
    uint32_t a;
    asm("{ .reg .u64 t; cvta.to.shared.u64 t, %1; cvt.u32.u64 %0, t; }"
        : "=r"(a) : "l"(p));
    return a;
}
__device__ __forceinline__ void ldm_x4(uint32_t& r0, uint32_t& r1,
                                       uint32_t& r2, uint32_t& r3, uint32_t a) {
    asm volatile("ldmatrix.sync.aligned.m8n8.x4.shared.b16 {%0,%1,%2,%3}, [%4];"
                 : "=r"(r0), "=r"(r1), "=r"(r2), "=r"(r3) : "r"(a));
}
// m16n8k8 TF32 MMA. A frag 4 regs, B frag 2 regs, C/D 4 f32.
__device__ __forceinline__ void mma168_tf32(float* c, const uint32_t* a,
                                            const uint32_t* b) {
    asm volatile(
        "mma.sync.aligned.m16n8k8.row.col.f32.tf32.tf32.f32 "
        "{%0,%1,%2,%3}, {%4,%5,%6,%7}, {%8,%9}, {%0,%1,%2,%3};"
        : "+f"(c[0]), "+f"(c[1]), "+f"(c[2]), "+f"(c[3])
        : "r"(a[0]), "r"(a[1]), "r"(a[2]), "r"(a[3]), "r"(b[0]), "r"(b[1]));
}
__device__ __forceinline__ void cpa16(uint32_t s, const void* g) {
    asm volatile("cp.async.cg.shared.global [%0], [%1], 16;"
                 :: "r"(s), "l"(g) : "memory");
}
#define CP_COMMIT() asm volatile("cp.async.commit_group;" ::: "memory")
#define CP_WAIT2()  asm volatile("cp.async.wait_group 2;" ::: "memory")

// Round f32 bits to nearest tf32 (13 low mantissa bits): +0x1000, HW truncates.
#define RN_TF32(r) ((r) + 0x1000u)

// 128B rows, 8 x 16B chunks, full XOR swizzle: chunk ^= row&7.
#define SWOFF2(row, c) ((row) * 128 + ((((c) ^ ((row) & 7))) << 4))

// ---------------------------------------------------------------------------
// TF32 mma.sync GEMM on RAW fp32 inputs.
//   C[64,64] tile = x[64,256] @ W[64,256]^T + bias
// 256 threads / 8 warps, warp tile 16(M) x 32(N) (warp grid 4x2).
// K-step 32 floats (128B rows), 4-stage cp.async with wait_group 2
// (two tile-loads in flight). Dynamic smem 64KB (3 CTAs/SM).
// Grid 32 x 4 x 3 = 384 CTAs (~3072 warps chip-wide).
// ---------------------------------------------------------------------------
__global__ __launch_bounds__(256) void mma_gemm(
    const float* __restrict__ X,
    const float* __restrict__ Wq, const float* __restrict__ Wk,
    const float* __restrict__ Wv,
    const float* __restrict__ bq, const float* __restrict__ bk,
    const float* __restrict__ bv)
{
    extern __shared__ __align__(16) char smem[];
    // [NST stages of A: 8KB][NST stages of B: 8KB]

    const int tid  = threadIdx.x;
    const int lane = tid & 31;
    const int wid  = tid >> 5;
    const int warp_m = wid & 3;          // 4 x m16 = 64 M
    const int warp_n = wid >> 2;         // 2 x n32 = 64 N

    const int row0 = blockIdx.x * 64;
    const int col0 = blockIdx.y * 64;
    const int z    = blockIdx.z;
    const float* Wg   = (z == 0) ? Wq : (z == 1) ? Wk : Wv;
    const float* bias = (z == 0) ? bq : (z == 1) ? bk : bv;
    float* Cw = (z == 0) ? g_Q : (z == 1) ? g_K : g_V;

    // loader: thread -> (row, 2 x 16B chunks); k-tile = 32 floats = 8 chunks
    const int lrow  = tid >> 2;          // 0..63
    const int cbase = (tid & 3) * 2;     // 0,2,4,6
    const float* agp = X  + (size_t)(row0 + lrow) * D + cbase * 4;
    const float* bgp = Wg + (size_t)(col0 + lrow) * D + cbase * 4;
    const uint32_t sA_base = smem_u32(smem);
    const uint32_t sB_base = sA_base + NST * 8192;
    uint32_t saoff[2], sboff[2];
    #pragma unroll
    for (int j = 0; j < 2; j++) {
        saoff[j] = sA_base + SWOFF2(lrow, cbase + j);
        sboff[j] = sB_base + SWOFF2(lrow, cbase + j);
    }

    // ldmatrix fragment addresses over 4 k8-steps per 128B row.
    // A: 1 frag (m16); B: 2 frag groups (2 x n16).
    uint32_t aaddr[4], baddr[2][4];
    {
        const int m = lane >> 3;
        const int ar  = ((m & 1) << 3) + (lane & 7);
        const int akc = m >> 1;
        const int bn  = ((m >> 1) << 3) + (lane & 7);
        const int bkc = m & 1;
        {
            const int row = warp_m * 16 + ar;
            #pragma unroll
            for (int h = 0; h < 4; h++)
                aaddr[h] = sA_base + SWOFF2(row, akc + 2 * h);
        }
        #pragma unroll
        for (int g = 0; g < 2; g++) {
            const int row = warp_n * 32 + g * 16 + bn;
            #pragma unroll
            for (int h = 0; h < 4; h++)
                baddr[g][h] = sB_base + SWOFF2(row, bkc + 2 * h);
        }
    }

    float acc[4][4];                      // [n8-group][quad]
    #pragma unroll
    for (int g = 0; g < 4; g++)
        #pragma unroll
        for (int i = 0; i < 4; i++) acc[g][i] = 0.f;

    // prologue: stages 0..2
    #pragma unroll
    for (int st = 0; st < NST - 1; st++) {
        const uint32_t so = st * 8192;
        #pragma unroll
        for (int j = 0; j < 2; j++) {
            cpa16(saoff[j] + so, agp + st * 32 + j * 4);
            cpa16(sboff[j] + so, bgp + st * 32 + j * 4);
        }
        CP_COMMIT();
    }

    for (int it = 0; it < KTILES; it++) {
        CP_WAIT2();              // tile `it` landed (2 newer may be in flight)
        __syncthreads();         // all warps done with buffer (it+3)&3's old data

        const int nst = it + NST - 1;
        if (nst < KTILES) {
            const uint32_t so = (nst & (NST - 1)) * 8192;
            #pragma unroll
            for (int j = 0; j < 2; j++) {
                cpa16(saoff[j] + so, agp + nst * 32 + j * 4);
                cpa16(sboff[j] + so, bgp + nst * 32 + j * 4);
            }
        }
        CP_COMMIT();

        const uint32_t so = (it & (NST - 1)) * 8192;
        #pragma unroll
        for (int h = 0; h < 4; h++) {
            uint32_t af[4], bfr[2][4];
            ldm_x4(af[0], af[1], af[2], af[3], aaddr[h] + so);
            ldm_x4(bfr[0][0], bfr[0][1], bfr[0][2], bfr[0][3], baddr[0][h] + so);
            ldm_x4(bfr[1][0], bfr[1][1], bfr[1][2], bfr[1][3], baddr[1][h] + so);
            // unbiased round-to-nearest-tf32
            #pragma unroll
            for (int i = 0; i < 4; i++) af[i] = RN_TF32(af[i]);
            #pragma unroll
            for (int g = 0; g < 2; g++)
                #pragma unroll
                for (int i = 0; i < 4; i++) bfr[g][i] = RN_TF32(bfr[g][i]);
            #pragma unroll
            for (int g = 0; g < 2; g++) {
                mma168_tf32(acc[2 * g + 0], af, &bfr[g][0]);
                mma168_tf32(acc[2 * g + 1], af, &bfr[g][2]);
            }
        }
    }

    // epilogue: add bias, store fp32 (warp tile m16 x n32)
    const int tg = lane >> 2;
    const int tc = (lane & 3) * 2;
    const int rbase = row0 + warp_m * 16 + tg;
    #pragma unroll
    for (int g = 0; g < 4; g++) {
        const int c = col0 + warp_n * 32 + g * 8 + tc;
        const float b0 = bias[c], b1 = bias[c + 1];
        float2 v0 = { acc[g][0] + b0, acc[g][1] + b1 };
        float2 v1 = { acc[g][2] + b0, acc[g][3] + b1 };
        *(float2*)&Cw[(size_t)rbase * D + c]       = v0;
        *(float2*)&Cw[(size_t)(rbase + 8) * D + c] = v1;
    }
}

// ---------------------------------------------------------------------------
// Attention via rank-13 Taylor factorization of exp(q*k/16).
// 256 CTAs x 8 warps (one warp per token). Lane owns 8 contiguous elements.
// ---------------------------------------------------------------------------
__global__ __launch_bounds__(256) void attn_kernel(float* __restrict__ out)
{
    const int lane = threadIdx.x & 31;
    const int t = blockIdx.x * 8 + (threadIdx.x >> 5);
    const int base = t * D;
    const int eb = base + lane * 8;
    const float s = 1.0f / 16.0f;

    float4 k4a = *(const float4*)&g_K[eb];
    float4 k4b = *(const float4*)&g_K[eb + 4];
    float4 v4a = *(const float4*)&g_V[eb];
    float4 v4b = *(const float4*)&g_V[eb + 4];
    float4 q4a = *(const float4*)&g_Q[eb];
    float4 q4b = *(const float4*)&g_Q[eb + 4];

    float kv[8] = { k4a.x * s, k4a.y * s, k4a.z * s, k4a.w * s,
                    k4b.x * s, k4b.y * s, k4b.z * s, k4b.w * s };
    float vv[8] = { v4a.x, v4a.y, v4a.z, v4a.w, v4b.x, v4b.y, v4b.z, v4b.w };
    float qv[8] = { q4a.x, q4a.y, q4a.z, q4a.w, q4b.x, q4b.y, q4b.z, q4b.w };

    float m[13], M[13];
    #pragma unroll
    for (int n = 0; n < 13; n++) { m[n] = 0.f; M[n] = 0.f; }
    #pragma unroll
    for (int u = 0; u < 8; u++) {
        const float k1 = kv[u], v1 = vv[u];
        M[0] += v1;
        float kp = k1;
        m[1] += kp; M[1] += kp * v1;
        #pragma unroll
        for (int n = 2; n <= 12; n++) {
            kp *= k1;
            m[n] += kp;
            M[n] += kp * v1;
        }
    }
    m[0] = 8.0f;

    #pragma unroll
    for (int off = 16; off; off >>= 1) {
        #pragma unroll
        for (int n = 0; n < 13; n++) {
            m[n] += __shfl_xor_sync(0xFFFFFFFFu, m[n], off);
            M[n] += __shfl_xor_sync(0xFFFFFFFFu, M[n], off);
        }
    }

    const float invf[13] = {
        1.f, 1.f, 0.5f, 1.f/6.f, 1.f/24.f, 1.f/120.f, 1.f/720.f,
        1.f/5040.f, 1.f/40320.f, 1.f/362880.f, 1.f/3628800.f,
        1.f/39916800.f, 1.f/479001600.f };
    #pragma unroll
    for (int n = 2; n < 13; n++) { m[n] *= invf[n]; M[n] *= invf[n]; }

    float res[8];
    #pragma unroll
    for (int u = 0; u < 8; u++) {
        const float q = qv[u];
        float num = M[12], den = m[12];
        #pragma unroll
        for (int n = 11; n >= 0; n--) {
            num = num * q + M[n];
            den = den * q + m[n];
        }
        res[u] = __fdividef(num, den);
    }
    *(float4*)&out[eb]     = make_float4(res[0], res[1], res[2], res[3]);
    *(float4*)&out[eb + 4] = make_float4(res[4], res[5], res[6], res[7]);
}

// ---------------------------------------------------------------------------
// Launch. Inputs: x, Wq, bq, Wk, bk, Wv, bv. Output fp32 [2,1024,256].
// ---------------------------------------------------------------------------
extern "C" void kernel_launch(void* const* d_in, const int* in_sizes, int n_in,
                              void* d_out, int out_size)
{
    const float* x  = (const float*)d_in[0];
    const float* Wq = (const float*)d_in[1];
    const float* bq = (const float*)d_in[2];
    const float* Wk = (const float*)d_in[3];
    const float* bk = (const float*)d_in[4];
    const float* Wv = (const float*)d_in[5];
    const float* bv = (const float*)d_in[6];
    float* out = (float*)d_out;

    static bool attr_set = false;
    if (!attr_set) {
        cudaFuncSetAttribute(mma_gemm,
                             cudaFuncAttributeMaxDynamicSharedMemorySize,
                             NST * 16384);
        attr_set = true;
    }

    dim3 ggrid(BT / 64, D / 64, 3);   // 32 x 4 x 3 = 384 CTAs
    mma_gemm<<<ggrid, 256, NST * 16384>>>(x, Wq, Wk, Wv, bq, bk, bv);
    attn_kernel<<<BT / 8, 256>>>(out);
}